// round 6
// baseline (speedup 1.0000x reference)
#include <cuda_runtime.h>
#include <cuda_fp16.h>

#define B_  4
#define C_  192
#define S_  64
#define L_  512

// ctx[b][s][c] scratch (196,608 bytes)
__device__ float g_ctx[B_ * S_ * C_];

// ---------------------------------------------------------------------------
// Kernel 1: per (b,s): q = wq . query + bq ; softmax over L ;
// kctx[c] = sum_l scores[l]*key[c,l] ; ctx = Wk @ kctx + bk  -> g_ctx
// grid = B*S = 256 blocks, 512 threads
// ---------------------------------------------------------------------------
#define K1_SMEM_FLOATS (192*193 + 192 + 512 + 192 + 64)
#define K1_SMEM_BYTES  (K1_SMEM_FLOATS * 4)

__global__ __launch_bounds__(512, 1)
void attn_ctx_kernel(const float* __restrict__ query,
                     const float* __restrict__ key,
                     const float* __restrict__ ipw,
                     const float* __restrict__ ipb)
{
    extern __shared__ float sm1[];
    float* wk_s   = sm1;                    // 192 x 193 (padded, conflict-free rows)
    float* wq_s   = wk_s + 192 * 193;       // 192
    float* scores = wq_s + 192;             // 512
    float* kctx   = scores + 512;           // 192
    float* red    = kctx + 192;             // 64

    const int bs   = blockIdx.x;
    const int b    = bs >> 6;
    const int s    = bs & 63;
    const int tid  = threadIdx.x;
    const int lane = tid & 31;
    const int warp = tid >> 5;

    // stage wq and Wk into smem (coalesced gmem reads)
    for (int i = tid; i < 192; i += 512) wq_s[i] = ipw[i];
    for (int i = tid; i < 192 * 192; i += 512) {
        int o = i / 192, c = i - o * 192;
        wk_s[o * 193 + c] = ipw[(1 + o) * 192 + c];
    }
    __syncthreads();

    // ---- stage 1: q[l] for l = tid ----
    const float* qp = query + (((size_t)b * C_) * S_ + s) * (size_t)L_ + tid;
    float acc = 0.f;
#pragma unroll 4
    for (int c = 0; c < C_; c++)
        acc = fmaf(wq_s[c], qp[(size_t)c * (S_ * L_)], acc);
    float q = acc + ipb[0];

    // ---- softmax over the 512 threads ----
    float v = q;
#pragma unroll
    for (int off = 16; off; off >>= 1)
        v = fmaxf(v, __shfl_xor_sync(0xffffffffu, v, off));
    if (lane == 0) red[warp] = v;
    __syncthreads();
    if (warp == 0) {
        float m = (lane < 16) ? red[lane] : -1e30f;
#pragma unroll
        for (int off = 16; off; off >>= 1)
            m = fmaxf(m, __shfl_xor_sync(0xffffffffu, m, off));
        if (lane == 0) red[32] = m;
    }
    __syncthreads();
    float e = __expf(q - red[32]);
    scores[tid] = e;

    v = e;
#pragma unroll
    for (int off = 16; off; off >>= 1)
        v += __shfl_xor_sync(0xffffffffu, v, off);
    if (lane == 0) red[16 + warp] = v;
    __syncthreads();
    if (warp == 0) {
        float m = (lane < 16) ? red[16 + lane] : 0.f;
#pragma unroll
        for (int off = 16; off; off >>= 1)
            m += __shfl_xor_sync(0xffffffffu, m, off);
        if (lane == 0) red[33] = m;
    }
    __syncthreads();
    float inv = 1.f / red[33];
    scores[tid] = e * inv;
    __syncthreads();

    // ---- stage 2: kctx[c] = sum_l scores[l] * key[b,c,s,l] ----
    for (int c = warp; c < C_; c += 16) {
        const float* kp = key + (((size_t)b * C_ + c) * S_ + s) * (size_t)L_;
        float a = 0.f;
#pragma unroll 4
        for (int l = lane; l < L_; l += 32)
            a = fmaf(scores[l], kp[l], a);
#pragma unroll
        for (int off = 16; off; off >>= 1)
            a += __shfl_xor_sync(0xffffffffu, a, off);
        if (lane == 0) kctx[c] = a;
    }
    __syncthreads();

    // ---- stage 3: ctx = Wk @ kctx + bk ----
    if (tid < C_) {
        float a = 0.f;
#pragma unroll 8
        for (int c = 0; c < C_; c++)
            a = fmaf(wk_s[tid * 193 + c], kctx[c], a);
        g_ctx[(size_t)bs * C_ + tid] = a + ipb[1 + tid];
    }
}

// ---------------------------------------------------------------------------
// Kernel 2: per (b,s): out = Wo @ (relu(Wv @ X + bv) * ctx) + bo
// fp16 mma.sync m16n8k16, fp32 accumulate. grid = 256, 256 threads (8 warps).
// Warp tiling: 4 (m) x 2 (n); warp tile m48 x n32; N subtile = 64, 8 subtiles.
// ---------------------------------------------------------------------------
#define PA 200   // half pitch for weight tiles (bank stride 4 words: conflict-free frags)
#define PX 202   // half pitch for X/T tiles (odd word pitch: conflict-free transpose store)
#define NSUB 64

#define K2_SMEM_BYTES ((2 * 192 * PA + 2 * NSUB * PX) * 2 + 3 * 192 * 4)

__device__ __forceinline__ void mma16816(float* c, const unsigned* a, const unsigned* bf)
{
    asm volatile(
        "mma.sync.aligned.m16n8k16.row.col.f32.f16.f16.f32 "
        "{%0,%1,%2,%3},{%4,%5,%6,%7},{%8,%9},{%0,%1,%2,%3};\n"
        : "+f"(c[0]), "+f"(c[1]), "+f"(c[2]), "+f"(c[3])
        : "r"(a[0]), "r"(a[1]), "r"(a[2]), "r"(a[3]), "r"(bf[0]), "r"(bf[1]));
}

// D(192 x 64) = A(192 x 192) * B^T, A row-major [m][k] pitch PA,
// B stored [n][k] pitch PX (i.e. K x N col-major). Per-warp m48 x n32 tile.
__device__ __forceinline__ void gemm192(const __half* __restrict__ Asm,
                                        const __half* __restrict__ Bsm,
                                        int mb, int nb, int g, int tg,
                                        float acc[3][4][4])
{
#pragma unroll
    for (int mi = 0; mi < 3; mi++)
#pragma unroll
        for (int ni = 0; ni < 4; ni++)
#pragma unroll
            for (int r = 0; r < 4; r++) acc[mi][ni][r] = 0.f;

#pragma unroll
    for (int kk = 0; kk < 12; kk++) {
        const int k0 = kk * 16;
        unsigned a[3][4];
#pragma unroll
        for (int mi = 0; mi < 3; mi++) {
            const __half* ap = Asm + (mb + mi * 16 + g) * PA + k0 + 2 * tg;
            a[mi][0] = *(const unsigned*)(ap);
            a[mi][1] = *(const unsigned*)(ap + 8 * PA);
            a[mi][2] = *(const unsigned*)(ap + 8);
            a[mi][3] = *(const unsigned*)(ap + 8 * PA + 8);
        }
        unsigned bf[4][2];
#pragma unroll
        for (int ni = 0; ni < 4; ni++) {
            const __half* bp = Bsm + (nb + ni * 8 + g) * PX + k0 + 2 * tg;
            bf[ni][0] = *(const unsigned*)(bp);
            bf[ni][1] = *(const unsigned*)(bp + 8);
        }
#pragma unroll
        for (int mi = 0; mi < 3; mi++)
#pragma unroll
            for (int ni = 0; ni < 4; ni++)
                mma16816(acc[mi][ni], a[mi], bf[ni]);
    }
}

__global__ __launch_bounds__(256, 1)
void fused_vproj_out_kernel(const float* __restrict__ value,
                            const float* __restrict__ ipw,
                            const float* __restrict__ ipb,
                            const float* __restrict__ opw,
                            const float* __restrict__ opb,
                            float* __restrict__ out)
{
    extern __shared__ char sm2[];
    __half* A1 = (__half*)sm2;            // Wv  192 x PA
    __half* A2 = A1 + 192 * PA;           // Wo  192 x PA
    __half* Xs = A2 + 192 * PA;           // X^T NSUB x PX  ([n][k], k = channel)
    __half* Ts = Xs + NSUB * PX;          // T^T NSUB x PX
    float* ctx_s = (float*)(Ts + NSUB * PX);
    float* bv_s  = ctx_s + 192;
    float* bo_s  = bv_s + 192;

    const int bs   = blockIdx.x;
    const int b    = bs >> 6;
    const int s    = bs & 63;
    const int tid  = threadIdx.x;
    const int lane = tid & 31;
    const int warp = tid >> 5;
    const int g    = lane >> 2;
    const int tg   = lane & 3;
    const int mb   = (warp >> 1) * 48;
    const int nb   = (warp & 1) * 32;

    // stage weights (fp32 gmem -> fp16 smem), ctx, biases
    for (int i = tid; i < 192 * 192; i += 256) {
        int o = i / 192, c = i - o * 192;
        A1[o * PA + c] = __float2half(ipw[(1 + C_ + o) * C_ + c]);
        A2[o * PA + c] = __float2half(opw[i]);
    }
    for (int i = tid; i < 192; i += 256) {
        ctx_s[i] = g_ctx[(size_t)bs * C_ + i];
        bv_s[i]  = ipb[1 + C_ + i];
        bo_s[i]  = opb[i];
    }
    __syncthreads();

    const float* vbase = value + (((size_t)b * C_) * S_ + s) * (size_t)L_;
    float*       obase = out   + (((size_t)b * C_) * S_ + s) * (size_t)L_;

    float acc[3][4][4];

    for (int it = 0; it < L_ / NSUB; it++) {
        const int n0 = it * NSUB;

        // stage X subtile: value[c, n0+l] -> Xs[l][c] (fp16, transposed)
        for (int i = tid; i < C_ * NSUB; i += 256) {
            int c = i >> 6, l = i & 63;
            Xs[l * PX + c] = __float2half(vbase[(size_t)c * (S_ * L_) + n0 + l]);
        }
        __syncthreads();

        // GEMM1: T = relu(Wv @ X + bv) * ctx  (epilogue writes T^T to smem)
        gemm192(A1, Xs, mb, nb, g, tg, acc);
#pragma unroll
        for (int mi = 0; mi < 3; mi++) {
            const int row = mb + mi * 16 + g;
            const float bvl = bv_s[row],     cxl = ctx_s[row];
            const float bvh = bv_s[row + 8], cxh = ctx_s[row + 8];
#pragma unroll
            for (int ni = 0; ni < 4; ni++) {
                const int n = nb + ni * 8 + 2 * tg;
                Ts[n * PX + row]           = __float2half(fmaxf(acc[mi][ni][0] + bvl, 0.f) * cxl);
                Ts[(n + 1) * PX + row]     = __float2half(fmaxf(acc[mi][ni][1] + bvl, 0.f) * cxl);
                Ts[n * PX + row + 8]       = __float2half(fmaxf(acc[mi][ni][2] + bvh, 0.f) * cxh);
                Ts[(n + 1) * PX + row + 8] = __float2half(fmaxf(acc[mi][ni][3] + bvh, 0.f) * cxh);
            }
        }
        __syncthreads();

        // GEMM2: out = Wo @ T + bo  -> gmem (float2 stores)
        gemm192(A2, Ts, mb, nb, g, tg, acc);
#pragma unroll
        for (int mi = 0; mi < 3; mi++) {
            const int row = mb + mi * 16 + g;
            const float bl = bo_s[row], bh = bo_s[row + 8];
            float* o0 = obase + (size_t)row * (S_ * L_) + n0;
#pragma unroll
            for (int ni = 0; ni < 4; ni++) {
                const int n = nb + ni * 8 + 2 * tg;
                float2 lo = make_float2(acc[mi][ni][0] + bl, acc[mi][ni][1] + bl);
                float2 hi = make_float2(acc[mi][ni][2] + bh, acc[mi][ni][3] + bh);
                *(float2*)(o0 + n)                       = lo;
                *(float2*)(o0 + (size_t)8 * (S_ * L_) + n) = hi;
            }
        }
        __syncthreads();
    }
}

// ---------------------------------------------------------------------------
extern "C" void kernel_launch(void* const* d_in, const int* in_sizes, int n_in,
                              void* d_out, int out_size)
{
    const float* query = (const float*)d_in[0];
    const float* key   = (const float*)d_in[1];
    const float* value = (const float*)d_in[2];
    const float* ipw   = (const float*)d_in[3];
    const float* ipb   = (const float*)d_in[4];
    const float* opw   = (const float*)d_in[5];
    const float* opb   = (const float*)d_in[6];
    float* out = (float*)d_out;

    cudaFuncSetAttribute(attn_ctx_kernel,
                         cudaFuncAttributeMaxDynamicSharedMemorySize, K1_SMEM_BYTES);
    cudaFuncSetAttribute(fused_vproj_out_kernel,
                         cudaFuncAttributeMaxDynamicSharedMemorySize, K2_SMEM_BYTES);

    attn_ctx_kernel<<<B_ * S_, 512, K1_SMEM_BYTES>>>(query, key, ipw, ipb);
    fused_vproj_out_kernel<<<B_ * S_, 256, K2_SMEM_BYTES>>>(value, ipw, ipb, opw, opb, out);
}

// round 8
// speedup vs baseline: 1.9415x; 1.9415x over previous
#include <cuda_runtime.h>
#include <cuda_fp16.h>

#define B_  4
#define C_  192
#define S_  64
#define L_  512
#define SL_ (S_ * L_)

// ctx[b][s][c] scratch (196,608 bytes)
__device__ float g_ctx[B_ * S_ * C_];

// ---------------------------------------------------------------------------
// Kernel 1: per (b,s): q = wq . query + bq ; softmax over L ;
// kctx[c] = sum_l scores[l]*key[c,l] ; ctx = Wk @ kctx + bk  -> g_ctx
// grid = B*S = 256 blocks, 512 threads. Tiny smem -> 2 blocks/SM, all
// 256 blocks resident in one wave (streaming / BW-bound).
// ---------------------------------------------------------------------------
__global__ __launch_bounds__(512, 2)
void attn_ctx_kernel(const float* __restrict__ query,
                     const float* __restrict__ key,
                     const float* __restrict__ ipw,
                     const float* __restrict__ ipb)
{
    __shared__ float wq_s[192];
    __shared__ float scores[512];
    __shared__ float kctx[192];
    __shared__ float red[64];

    const int bs   = blockIdx.x;
    const int b    = bs >> 6;
    const int s    = bs & 63;
    const int tid  = threadIdx.x;
    const int lane = tid & 31;
    const int warp = tid >> 5;

    if (tid < 192) wq_s[tid] = ipw[tid];
    __syncthreads();

    // ---- stage 1: q[l] for l = tid ----
    const float* qp = query + (((size_t)b * C_) * S_ + s) * (size_t)L_ + tid;
    float a0 = 0.f, a1 = 0.f;
#pragma unroll 8
    for (int c = 0; c < C_; c += 2) {
        a0 = fmaf(wq_s[c],     qp[(size_t)c * SL_],       a0);
        a1 = fmaf(wq_s[c + 1], qp[(size_t)(c + 1) * SL_], a1);
    }
    float q = a0 + a1 + ipb[0];

    // ---- softmax over the 512 threads ----
    float v = q;
#pragma unroll
    for (int off = 16; off; off >>= 1)
        v = fmaxf(v, __shfl_xor_sync(0xffffffffu, v, off));
    if (lane == 0) red[warp] = v;
    __syncthreads();
    if (warp == 0) {
        float m = (lane < 16) ? red[lane] : -1e30f;
#pragma unroll
        for (int off = 16; off; off >>= 1)
            m = fmaxf(m, __shfl_xor_sync(0xffffffffu, m, off));
        if (lane == 0) red[32] = m;
    }
    __syncthreads();
    float e = __expf(q - red[32]);

    v = e;
#pragma unroll
    for (int off = 16; off; off >>= 1)
        v += __shfl_xor_sync(0xffffffffu, v, off);
    if (lane == 0) red[16 + warp] = v;
    __syncthreads();
    if (warp == 0) {
        float m = (lane < 16) ? red[16 + lane] : 0.f;
#pragma unroll
        for (int off = 16; off; off >>= 1)
            m += __shfl_xor_sync(0xffffffffu, m, off);
        if (lane == 0) red[33] = m;
    }
    __syncthreads();
    scores[tid] = e * (1.f / red[33]);
    __syncthreads();

    // ---- stage 2: kctx[c] = sum_l scores[l] * key[b,c,s,l] ----
    for (int c = warp; c < C_; c += 16) {
        const float* kp = key + (((size_t)b * C_ + c) * S_ + s) * (size_t)L_;
        float a = 0.f;
#pragma unroll 4
        for (int l = lane; l < L_; l += 32)
            a = fmaf(scores[l], kp[l], a);
#pragma unroll
        for (int off = 16; off; off >>= 1)
            a += __shfl_xor_sync(0xffffffffu, a, off);
        if (lane == 0) kctx[c] = a;
    }
    __syncthreads();

    // ---- stage 3: ctx = Wk @ kctx + bk (warp-per-row, coalesced gmem/L2) ----
#pragma unroll
    for (int j = 0; j < 12; j++) {
        const int o = warp * 12 + j;
        const float* wrow = ipw + (size_t)(1 + o) * C_;
        float a = 0.f;
#pragma unroll
        for (int k = 0; k < 6; k++) {
            int c = lane + k * 32;
            a = fmaf(wrow[c], kctx[c], a);
        }
#pragma unroll
        for (int off = 16; off; off >>= 1)
            a += __shfl_xor_sync(0xffffffffu, a, off);
        if (lane == 0) g_ctx[(size_t)bs * C_ + o] = a + ipb[1 + o];
    }
}

// ---------------------------------------------------------------------------
// Kernel 2: per (b,s): out = Wo @ (relu(Wv @ X + bv) * ctx) + bo
// fp16 mma.sync m16n8k16, fp32 accumulate. grid = 256, 512 threads (16 warps).
// Warp tiling: 4 (m) x 4 (n); warp tile m48 x n16. N subtile = 64, 8 subtiles.
// X staging is software-pipelined through registers (prefetch next subtile
// under GEMM2).
// ---------------------------------------------------------------------------
#define PA 200   // half pitch, weights: word pitch 100 -> bank stride 4 -> conflict-free frags
#define PX 202   // half pitch, X/T tiles
#define NSUB 64
#define NPF  24  // prefetch floats per thread: 192*64/512

#define K2_SMEM_BYTES ((2 * 192 * PA + 2 * NSUB * PX) * 2 + 3 * 192 * 4)

__device__ __forceinline__ void mma16816(float* c, const unsigned* a, const unsigned* bf)
{
    asm volatile(
        "mma.sync.aligned.m16n8k16.row.col.f32.f16.f16.f32 "
        "{%0,%1,%2,%3},{%4,%5,%6,%7},{%8,%9},{%0,%1,%2,%3};\n"
        : "+f"(c[0]), "+f"(c[1]), "+f"(c[2]), "+f"(c[3])
        : "r"(a[0]), "r"(a[1]), "r"(a[2]), "r"(a[3]), "r"(bf[0]), "r"(bf[1]));
}

// D(192 x 64) = A(192 x 192) * B^T. A row-major [m][k] pitch PA,
// B stored [n][k] pitch PX. Per-warp m48 x n16 tile.
__device__ __forceinline__ void gemm192(const __half* __restrict__ Asm,
                                        const __half* __restrict__ Bsm,
                                        int mb, int nb, int g, int tg,
                                        float acc[3][2][4])
{
#pragma unroll
    for (int mi = 0; mi < 3; mi++)
#pragma unroll
        for (int ni = 0; ni < 2; ni++)
#pragma unroll
            for (int r = 0; r < 4; r++) acc[mi][ni][r] = 0.f;

#pragma unroll
    for (int kk = 0; kk < 12; kk++) {
        const int k0 = kk * 16;
        unsigned a[3][4];
#pragma unroll
        for (int mi = 0; mi < 3; mi++) {
            const __half* ap = Asm + (mb + mi * 16 + g) * PA + k0 + 2 * tg;
            a[mi][0] = *(const unsigned*)(ap);
            a[mi][1] = *(const unsigned*)(ap + 8 * PA);
            a[mi][2] = *(const unsigned*)(ap + 8);
            a[mi][3] = *(const unsigned*)(ap + 8 * PA + 8);
        }
        unsigned bf[2][2];
#pragma unroll
        for (int ni = 0; ni < 2; ni++) {
            const __half* bp = Bsm + (nb + ni * 8 + g) * PX + k0 + 2 * tg;
            bf[ni][0] = *(const unsigned*)(bp);
            bf[ni][1] = *(const unsigned*)(bp + 8);
        }
#pragma unroll
        for (int mi = 0; mi < 3; mi++)
#pragma unroll
            for (int ni = 0; ni < 2; ni++)
                mma16816(acc[mi][ni], a[mi], bf[ni]);
    }
}

__global__ __launch_bounds__(512, 1)
void fused_vproj_out_kernel(const float* __restrict__ value,
                            const float* __restrict__ ipw,
                            const float* __restrict__ ipb,
                            const float* __restrict__ opw,
                            const float* __restrict__ opb,
                            float* __restrict__ out)
{
    extern __shared__ char sm2[];
    __half* A1 = (__half*)sm2;            // Wv  192 x PA
    __half* A2 = A1 + 192 * PA;           // Wo  192 x PA
    __half* Xs = A2 + 192 * PA;           // X^T NSUB x PX  ([n][k], k = channel)
    __half* Ts = Xs + NSUB * PX;          // T^T NSUB x PX
    float* ctx_s = (float*)(Ts + NSUB * PX);
    float* bv_s  = ctx_s + 192;
    float* bo_s  = bv_s + 192;

    const int bs   = blockIdx.x;
    const int b    = bs >> 6;
    const int s    = bs & 63;
    const int tid  = threadIdx.x;
    const int lane = tid & 31;
    const int warp = tid >> 5;
    const int g    = lane >> 2;
    const int tg   = lane & 3;
    const int mb   = (warp >> 2) * 48;    // 4 m-groups
    const int nb   = (warp & 3) * 16;     // 4 n-groups

    const float* vbase = value + (((size_t)b * C_) * S_ + s) * (size_t)L_;
    float*       obase = out   + (((size_t)b * C_) * S_ + s) * (size_t)L_;

    // thread's fixed (c,l) slots for X staging
    const int c0 = tid >> 6;              // base channel (stride 8 per j)
    const int lx = tid & 63;              // column within subtile

    // prefetch subtile 0 into registers (overlaps weight staging below)
    float xr[NPF];
#pragma unroll
    for (int j = 0; j < NPF; j++)
        xr[j] = vbase[(size_t)(c0 + j * 8) * SL_ + lx];

    // stage weights (fp32 gmem -> fp16 smem), ctx, biases
    for (int i = tid; i < 192 * 192; i += 512) {
        int o = i / 192, c = i - o * 192;
        A1[o * PA + c] = __float2half(ipw[(1 + C_ + o) * C_ + c]);
        A2[o * PA + c] = __float2half(opw[i]);
    }
    if (tid < 192) {
        ctx_s[tid] = g_ctx[(size_t)bs * C_ + tid];
        bv_s[tid]  = ipb[1 + C_ + tid];
        bo_s[tid]  = opb[tid];
    }
    __syncthreads();

    float acc[3][2][4];

    for (int it = 0; it < L_ / NSUB; it++) {
        const int n0 = it * NSUB;

        // commit prefetched X subtile to smem (fp16, transposed)
#pragma unroll
        for (int j = 0; j < NPF; j++)
            Xs[lx * PX + c0 + j * 8] = __float2half(xr[j]);
        __syncthreads();

        // GEMM1: T = relu(Wv @ X + bv) * ctx  (epilogue writes T^T to smem)
        gemm192(A1, Xs, mb, nb, g, tg, acc);
#pragma unroll
        for (int mi = 0; mi < 3; mi++) {
            const int row = mb + mi * 16 + g;
            const float bvl = bv_s[row],     cxl = ctx_s[row];
            const float bvh = bv_s[row + 8], cxh = ctx_s[row + 8];
#pragma unroll
            for (int ni = 0; ni < 2; ni++) {
                const int n = nb + ni * 8 + 2 * tg;
                Ts[n * PX + row]           = __float2half(fmaxf(acc[mi][ni][0] + bvl, 0.f) * cxl);
                Ts[(n + 1) * PX + row]     = __float2half(fmaxf(acc[mi][ni][1] + bvl, 0.f) * cxl);
                Ts[n * PX + row + 8]       = __float2half(fmaxf(acc[mi][ni][2] + bvh, 0.f) * cxh);
                Ts[(n + 1) * PX + row + 8] = __float2half(fmaxf(acc[mi][ni][3] + bvh, 0.f) * cxh);
            }
        }
        __syncthreads();   // Ts ready; Xs fully consumed

        // prefetch next subtile — latency hidden under GEMM2
        if (it < L_ / NSUB - 1) {
            const int n1 = n0 + NSUB;
#pragma unroll
            for (int j = 0; j < NPF; j++)
                xr[j] = vbase[(size_t)(c0 + j * 8) * SL_ + n1 + lx];
        }

        // GEMM2: out = Wo @ T + bo  -> gmem (float2 stores)
        gemm192(A2, Ts, mb, nb, g, tg, acc);
#pragma unroll
        for (int mi = 0; mi < 3; mi++) {
            const int row = mb + mi * 16 + g;
            const float bl = bo_s[row], bh = bo_s[row + 8];
            float* o0 = obase + (size_t)row * SL_ + n0;
#pragma unroll
            for (int ni = 0; ni < 2; ni++) {
                const int n = nb + ni * 8 + 2 * tg;
                float2 lo = make_float2(acc[mi][ni][0] + bl, acc[mi][ni][1] + bl);
                float2 hi = make_float2(acc[mi][ni][2] + bh, acc[mi][ni][3] + bh);
                *(float2*)(o0 + n)                    = lo;
                *(float2*)(o0 + (size_t)8 * SL_ + n)  = hi;
            }
        }
        __syncthreads();   // Ts free for next iteration's epilogue
    }
}

// ---------------------------------------------------------------------------
extern "C" void kernel_launch(void* const* d_in, const int* in_sizes, int n_in,
                              void* d_out, int out_size)
{
    const float* query = (const float*)d_in[0];
    const float* key   = (const float*)d_in[1];
    const float* value = (const float*)d_in[2];
    const float* ipw   = (const float*)d_in[3];
    const float* ipb   = (const float*)d_in[4];
    const float* opw   = (const float*)d_in[5];
    const float* opb   = (const float*)d_in[6];
    float* out = (float*)d_out;

    cudaFuncSetAttribute(fused_vproj_out_kernel,
                         cudaFuncAttributeMaxDynamicSharedMemorySize, K2_SMEM_BYTES);

    attn_ctx_kernel<<<B_ * S_, 512>>>(query, key, ipw, ipb);
    fused_vproj_out_kernel<<<B_ * S_, 512, K2_SMEM_BYTES>>>(value, ipw, ipb, opw, opb, out);
}